// round 1
// baseline (speedup 1.0000x reference)
#include <cuda_runtime.h>
#include <cstdint>

// ---------------------------------------------------------------------------
// STN: conv(3x3)+relu+pool x3 -> mean -> dense x3 -> theta -> bilinear sample
// Shapes: x (16,256,256,32) f32, out (16,256,256,32) f32
// ---------------------------------------------------------------------------

typedef unsigned long long ull;

#define NB   16
#define HW   256
#define CCH  32

// scratch (static device globals; no allocations allowed)
__device__ float g_pool1[16 * 127 * 127 * 16];   // after stage 1
__device__ float g_pool2[16 * 62 * 62 * 32];     // after stage 2
__device__ float g_mean[16 * 32];                // spatial-sum accumulator
__device__ float g_theta[16 * 6];

// packed fp32x2 FMA (FFMA2): d.lo += a.lo*b.lo ; d.hi += a.hi*b.hi
__device__ __forceinline__ void fma2(ull& d, ull a, ull b) {
    asm("fma.rn.f32x2 %0, %1, %2, %0;" : "+l"(d) : "l"(a), "l"(b));
}

__device__ __forceinline__ float2 asF2(ull v) {
    float2 r;
    r.x = __uint_as_float((unsigned)(v & 0xffffffffULL));
    r.y = __uint_as_float((unsigned)(v >> 32));
    return r;
}

// ---------------------------------------------------------------------------
// Fused conv3x3(VALID) + bias + relu + maxpool2x2 (+ optional global-mean acc)
// Block: 8x8 pooled pixels (16x16 conv region, 18x18 input window), 256 thr.
// Thread layout: tid = pix*4 + g ; pix in [0,64), g in [0,4).
//   group g computes COUT/4 output channels as COUT/8 fp32x2 pairs.
// SMEM: input tile duplicated as float2 pairs [CIN][18*18], weights [9*CIN*COUT].
// ---------------------------------------------------------------------------
template<int CIN, int COUT>
__global__ __launch_bounds__(256)
void conv_pool_kernel(const float* __restrict__ in, int inDim,
                      const float* __restrict__ w, const float* __restrict__ bias,
                      float* __restrict__ out, int outDim, int tilesX,
                      float* __restrict__ meanAcc)
{
    constexpr int NP = COUT / 8;        // fp32x2 pairs per thread
    extern __shared__ float smem[];
    float2* sIn = (float2*)smem;                 // CIN * 324 float2
    float*  sW  = smem + CIN * 324 * 2;          // 9*CIN*COUT floats
    __shared__ float sMean[COUT];

    const int tid = threadIdx.x;
    const int b  = blockIdx.y;
    const int tX = blockIdx.x % tilesX;
    const int tY = blockIdx.x / tilesX;
    const int y0 = tY * 16, x0 = tX * 16;        // input window base

    // ---- load weights (co-contiguous, 16B aligned) ----
    constexpr int WN4 = 9 * CIN * COUT / 4;
    for (int i = tid; i < WN4; i += 256)
        ((float4*)sW)[i] = ((const float4*)w)[i];

    // ---- load 18x18xCIN input window, duplicated into float2 pairs ----
    constexpr int NCI4 = CIN / 4;
    for (int i = tid; i < 324 * NCI4; i += 256) {
        int ci4 = i % NCI4;
        int p   = i / NCI4;
        int ly = p / 18, lx = p - ly * 18;
        int gy = y0 + ly, gx = x0 + lx;
        float4 v = make_float4(0.f, 0.f, 0.f, 0.f);
        if (gy < inDim && gx < inDim)
            v = *(const float4*)(in + ((size_t)((b * inDim + gy) * inDim + gx)) * CIN + ci4 * 4);
        sIn[(ci4 * 4 + 0) * 324 + p] = make_float2(v.x, v.x);
        sIn[(ci4 * 4 + 1) * 324 + p] = make_float2(v.y, v.y);
        sIn[(ci4 * 4 + 2) * 324 + p] = make_float2(v.z, v.z);
        sIn[(ci4 * 4 + 3) * 324 + p] = make_float2(v.w, v.w);
    }
    __syncthreads();

    const int pix = tid >> 2, g = tid & 3;
    const int py = pix >> 3, px = pix & 7;
    const int co0 = g * (COUT / 4);

    ull acc[4][NP];
    #pragma unroll
    for (int i = 0; i < 4; i++)
        #pragma unroll
        for (int j = 0; j < NP; j++) acc[i][j] = 0ULL;

    #pragma unroll
    for (int ky = 0; ky < 3; ky++) {
        #pragma unroll
        for (int kx = 0; kx < 3; kx++) {
            const float2* pbase = sIn + (2 * py + ky) * 18 + (2 * px + kx);
            const float*  wb    = sW + (ky * 3 + kx) * CIN * COUT + co0;
            #pragma unroll 4
            for (int ci = 0; ci < CIN; ci++) {
                const float2* pl = pbase + ci * 324;
                ull a00 = *(const ull*)(pl);
                ull a01 = *(const ull*)(pl + 1);
                ull a10 = *(const ull*)(pl + 18);
                ull a11 = *(const ull*)(pl + 19);
                const ull* wp = (const ull*)(wb + ci * COUT);
                #pragma unroll
                for (int pp = 0; pp < NP; pp++) {
                    ull w2 = wp[pp];
                    fma2(acc[0][pp], a00, w2);
                    fma2(acc[1][pp], a01, w2);
                    fma2(acc[2][pp], a10, w2);
                    fma2(acc[3][pp], a11, w2);
                }
            }
        }
    }

    // ---- relu(max2x2 + bias) ----
    const int p = tY * 8 + py, q = tX * 8 + px;
    const bool valid = (p < outDim) && (q < outDim);
    float res[2 * NP];
    #pragma unroll
    for (int pp = 0; pp < NP; pp++) {
        float2 v0 = asF2(acc[0][pp]);
        float2 v1 = asF2(acc[1][pp]);
        float2 v2 = asF2(acc[2][pp]);
        float2 v3 = asF2(acc[3][pp]);
        float blo = bias[co0 + 2 * pp];
        float bhi = bias[co0 + 2 * pp + 1];
        res[2 * pp]     = fmaxf(fmaxf(fmaxf(v0.x, v1.x), fmaxf(v2.x, v3.x)) + blo, 0.f);
        res[2 * pp + 1] = fmaxf(fmaxf(fmaxf(v0.y, v1.y), fmaxf(v2.y, v3.y)) + bhi, 0.f);
    }

    if (out && valid) {
        float* o = out + ((size_t)((b * outDim + p) * outDim + q)) * COUT + co0;
        #pragma unroll
        for (int k = 0; k < (2 * NP) / 4; k++)
            ((float4*)o)[k] = make_float4(res[4 * k], res[4 * k + 1], res[4 * k + 2], res[4 * k + 3]);
    }

    if (meanAcc) {
        if (tid < COUT) sMean[tid] = 0.f;
        __syncthreads();
        if (valid) {
            #pragma unroll
            for (int k = 0; k < 2 * NP; k++)
                atomicAdd(&sMean[co0 + k], res[k]);
        }
        __syncthreads();
        if (tid < COUT) atomicAdd(&meanAcc[b * COUT + tid], sMean[tid]);
    }
}

// ---------------------------------------------------------------------------
__global__ void zero_mean_kernel() { g_mean[threadIdx.x] = 0.f; }

// mean -> dense(32->64 relu) -> dense(64->32 relu) -> dense(32->6) + db3
__global__ void head_kernel(const float* __restrict__ D1, const float* __restrict__ db1,
                            const float* __restrict__ D2, const float* __restrict__ db2,
                            const float* __restrict__ D3, const float* __restrict__ db3)
{
    __shared__ float h0[16 * 32], h1[16 * 64], h2[16 * 32];
    int tid = threadIdx.x; // 256

    for (int i = tid; i < 512; i += 256) h0[i] = g_mean[i] * (1.0f / 900.0f);
    __syncthreads();

    for (int i = tid; i < 16 * 64; i += 256) {
        int bb = i >> 6, j = i & 63;
        float s = db1[j];
        #pragma unroll 8
        for (int c = 0; c < 32; c++) s += h0[bb * 32 + c] * D1[c * 64 + j];
        h1[i] = fmaxf(s, 0.f);
    }
    __syncthreads();

    for (int i = tid; i < 512; i += 256) {
        int bb = i >> 5, j = i & 31;
        float s = db2[j];
        #pragma unroll 8
        for (int c = 0; c < 64; c++) s += h1[bb * 64 + c] * D2[c * 32 + j];
        h2[i] = fmaxf(s, 0.f);
    }
    __syncthreads();

    if (tid < 96) {
        int bb = tid / 6, j = tid % 6;
        float s = db3[j];
        #pragma unroll 8
        for (int c = 0; c < 32; c++) s += h2[bb * 32 + c] * D3[c * 6 + j];
        g_theta[tid] = s;
    }
}

// ---------------------------------------------------------------------------
// Bilinear sampler: 8 threads per output pixel (4 channels each, float4).
// xS = t00*xs[c] + t01*ys[r] + t02 ; yS = t10*xs[c] + t11*ys[r] + t12
// x = 0.5*(xS+1)*254, fm[b, y, x, :] gathers (weights from CLIPPED corners,
// matching the reference exactly).
// ---------------------------------------------------------------------------
__global__ __launch_bounds__(256)
void sampler_kernel(const float* __restrict__ x, float* __restrict__ out)
{
    int t = blockIdx.x * 256 + threadIdx.x;
    int lane = t & 7;
    int pix  = t >> 3;
    int c = pix & 255;
    int r = (pix >> 8) & 255;
    int b = pix >> 16;

    const float* th = g_theta + b * 6;
    float xs = -1.f + (float)c * (2.f / 255.f);
    float ys = -1.f + (float)r * (2.f / 255.f);
    float xS = th[0] * xs + th[1] * ys + th[2];
    float yS = th[3] * xs + th[4] * ys + th[5];
    float xf = 0.5f * ((xS + 1.f) * 254.f);
    float yf = 0.5f * ((yS + 1.f) * 254.f);

    int ix0 = (int)floorf(xf), iy0 = (int)floorf(yf);
    int ix1 = ix0 + 1, iy1 = iy0 + 1;
    ix0 = min(max(ix0, 0), 255); ix1 = min(max(ix1, 0), 255);
    iy0 = min(max(iy0, 0), 255); iy1 = min(max(iy1, 0), 255);

    float X0 = (float)ix0, X1 = (float)ix1, Y0 = (float)iy0, Y1 = (float)iy1;
    float wa = (X1 - xf) * (Y1 - yf);   // fm[y0, x0]
    float wb = (X1 - xf) * (yf - Y0);   // fm[y1, x0]
    float wc = (xf - X0) * (Y1 - yf);   // fm[y0, x1]
    float wd = (xf - X0) * (yf - Y0);   // fm[y1, x1]

    const float4* pa = (const float4*)(x + ((size_t)((b * 256 + iy0) * 256 + ix0)) * 32) + lane;
    const float4* pb = (const float4*)(x + ((size_t)((b * 256 + iy1) * 256 + ix0)) * 32) + lane;
    const float4* pc = (const float4*)(x + ((size_t)((b * 256 + iy0) * 256 + ix1)) * 32) + lane;
    const float4* pd = (const float4*)(x + ((size_t)((b * 256 + iy1) * 256 + ix1)) * 32) + lane;
    float4 Ia = *pa, Ib = *pb, Ic = *pc, Id = *pd;

    float4 o;
    o.x = wa * Ia.x + wb * Ib.x + wc * Ic.x + wd * Id.x;
    o.y = wa * Ia.y + wb * Ib.y + wc * Ic.y + wd * Id.y;
    o.z = wa * Ia.z + wb * Ib.z + wc * Ic.z + wd * Id.z;
    o.w = wa * Ia.w + wb * Ib.w + wc * Ic.w + wd * Id.w;
    ((float4*)out)[t] = o;
}

// ---------------------------------------------------------------------------
extern "C" void kernel_launch(void* const* d_in, const int* in_sizes, int n_in,
                              void* d_out, int out_size)
{
    const float* x   = (const float*)d_in[0];
    const float* W1  = (const float*)d_in[1];
    const float* b1  = (const float*)d_in[2];
    const float* W2  = (const float*)d_in[3];
    const float* b2  = (const float*)d_in[4];
    const float* W3  = (const float*)d_in[5];
    const float* b3  = (const float*)d_in[6];
    const float* D1  = (const float*)d_in[7];
    const float* db1 = (const float*)d_in[8];
    const float* D2  = (const float*)d_in[9];
    const float* db2 = (const float*)d_in[10];
    const float* D3  = (const float*)d_in[11];
    const float* db3 = (const float*)d_in[12];
    float* out = (float*)d_out;

    float *p1, *p2, *mean_;
    cudaGetSymbolAddress((void**)&p1, g_pool1);
    cudaGetSymbolAddress((void**)&p2, g_pool2);
    cudaGetSymbolAddress((void**)&mean_, g_mean);

    const int SMEM1 = (32 * 324 * 2 + 9 * 32 * 16) * 4;   // 101376
    const int SMEM2 = (16 * 324 * 2 + 9 * 16 * 32) * 4;   //  59904
    const int SMEM3 = (32 * 324 * 2 + 9 * 32 * 32) * 4;   // 119808
    cudaFuncSetAttribute((const void*)conv_pool_kernel<32, 16>,
                         cudaFuncAttributeMaxDynamicSharedMemorySize, SMEM1);
    cudaFuncSetAttribute((const void*)conv_pool_kernel<16, 32>,
                         cudaFuncAttributeMaxDynamicSharedMemorySize, SMEM2);
    cudaFuncSetAttribute((const void*)conv_pool_kernel<32, 32>,
                         cudaFuncAttributeMaxDynamicSharedMemorySize, SMEM3);

    zero_mean_kernel<<<1, 512>>>();

    // stage 1: (16,256,256,32) -> (16,127,127,16) ; tiles 16x16
    conv_pool_kernel<32, 16><<<dim3(16 * 16, 16), 256, SMEM1>>>(
        x, 256, W1, b1, p1, 127, 16, nullptr);

    // stage 2: (16,127,127,16) -> (16,62,62,32) ; tiles 8x8
    conv_pool_kernel<16, 32><<<dim3(8 * 8, 16), 256, SMEM2>>>(
        p1, 127, W2, b2, p2, 62, 8, nullptr);

    // stage 3: (16,62,62,32) -> global-mean sums (pooled3 never stored)
    conv_pool_kernel<32, 32><<<dim3(4 * 4, 16), 256, SMEM3>>>(
        p2, 62, W3, b3, nullptr, 30, 4, mean_);

    head_kernel<<<1, 256>>>(D1, db1, D2, db2, D3, db3);

    // sampler: 16*256*256 pixels * 8 threads = 8.39M threads
    sampler_kernel<<<32768, 256>>>(x, out);
}

// round 2
// speedup vs baseline: 1.3054x; 1.3054x over previous
#include <cuda_runtime.h>
#include <cstdint>

// ---------------------------------------------------------------------------
// STN: conv(3x3)+relu+pool x3 -> mean -> dense x3 -> theta -> bilinear sample
// Shapes: x (16,256,256,32) f32, out (16,256,256,32) f32
// ---------------------------------------------------------------------------

typedef unsigned long long ull;

// scratch (static device globals; no allocations allowed)
__device__ float g_pool1[16 * 127 * 127 * 16];   // after stage 1
__device__ float g_pool2[16 * 62 * 62 * 32];     // after stage 2
__device__ float g_mean[16 * 32];                // spatial-sum accumulator
__device__ float g_theta[16 * 6];

// packed fp32x2 FMA (FFMA2): d.lo += a.lo*b.lo ; d.hi += a.hi*b.hi
__device__ __forceinline__ void fma2(ull& d, ull a, ull b) {
    asm("fma.rn.f32x2 %0, %1, %2, %0;" : "+l"(d) : "l"(a), "l"(b));
}

__device__ __forceinline__ float2 asF2(ull v) {
    float2 r;
    r.x = __uint_as_float((unsigned)(v & 0xffffffffULL));
    r.y = __uint_as_float((unsigned)(v >> 32));
    return r;
}

// ---------------------------------------------------------------------------
// Fused conv3x3(VALID) + bias + relu + maxpool2x2 (+ optional global-mean acc)
// fp32x2 packing over INPUT-CHANNEL pairs (K-dim vectorization):
//   acc[pos][cc] = (sum over even ci, sum over odd ci); horizontal add at end.
// Input smem [p][ci] (NHWC-natural, pad 4) -> LDS.64 channel pairs, no dup.
// Weight smem [k][co][ci] transposed (pad 2)  -> LDS.64 channel pairs, no dup.
// Block: 256 thr = 64 pooled pixels (8x8 tile) x 4 channel groups.
// Group g handles interleaved channels co = g + 4*cc (bank-conflict-free).
// ---------------------------------------------------------------------------
template<int CIN, int COUT>
__global__ __launch_bounds__(256)
void conv_pool_kernel(const float* __restrict__ in, int inDim,
                      const float* __restrict__ w, const float* __restrict__ bias,
                      float* __restrict__ out, int outDim, int tilesX,
                      float* __restrict__ meanAcc)
{
    constexpr int NC   = COUT / 4;   // channels per thread
    constexpr int ISTR = CIN + 4;    // input smem row stride (floats)
    constexpr int WSTR = CIN + 2;    // weight smem row stride (floats)
    extern __shared__ float smem[];
    float* sIn = smem;                       // 324 * ISTR
    float* sW  = smem + 324 * ISTR;          // 9 * COUT * WSTR
    __shared__ float sMean[COUT];

    const int tid = threadIdx.x;
    const int b  = blockIdx.y;
    const int tX = blockIdx.x % tilesX;
    const int tY = blockIdx.x / tilesX;
    const int y0 = tY * 16, x0 = tX * 16;    // input window base

    // ---- load weights with transpose: w[k][ci][co] -> sW[k][co][ci] ----
    constexpr int WTOT = 9 * CIN * COUT;
    for (int i = tid; i < WTOT; i += 256) {
        int co = i % COUT;
        int rest = i / COUT;
        int ci = rest % CIN;
        int k  = rest / CIN;
        sW[(k * COUT + co) * WSTR + ci] = w[i];
    }

    // ---- load 18x18xCIN input window (channels contiguous, no dup) ----
    constexpr int NCI4 = CIN / 4;
    for (int i = tid; i < 324 * NCI4; i += 256) {
        int ci4 = i % NCI4;
        int p   = i / NCI4;
        int ly = p / 18, lx = p - ly * 18;
        int gy = y0 + ly, gx = x0 + lx;
        float4 v = make_float4(0.f, 0.f, 0.f, 0.f);
        if (gy < inDim && gx < inDim)
            v = *(const float4*)(in + ((size_t)((b * inDim + gy) * inDim + gx)) * CIN + ci4 * 4);
        *(float4*)(sIn + p * ISTR + ci4 * 4) = v;
    }
    __syncthreads();

    const int pix = tid >> 2, g = tid & 3;
    const int py = pix >> 3, px = pix & 7;

    ull acc[4][NC];
    #pragma unroll
    for (int i = 0; i < 4; i++)
        #pragma unroll
        for (int j = 0; j < NC; j++) acc[i][j] = 0ULL;

    #pragma unroll
    for (int ky = 0; ky < 3; ky++) {
        #pragma unroll
        for (int kx = 0; kx < 3; kx++) {
            const float* ib = sIn + ((2 * py + ky) * 18 + (2 * px + kx)) * ISTR;
            const float* wb = sW + (ky * 3 + kx) * COUT * WSTR + g * WSTR;
            #pragma unroll 4
            for (int c2 = 0; c2 < CIN / 2; c2++) {
                ull a00 = *(const ull*)(ib + 2 * c2);
                ull a01 = *(const ull*)(ib + ISTR + 2 * c2);
                ull a10 = *(const ull*)(ib + 18 * ISTR + 2 * c2);
                ull a11 = *(const ull*)(ib + 19 * ISTR + 2 * c2);
                const float* wp = wb + 2 * c2;
                #pragma unroll
                for (int cc = 0; cc < NC; cc++) {
                    ull w2 = *(const ull*)(wp + cc * 4 * WSTR);
                    fma2(acc[0][cc], a00, w2);
                    fma2(acc[1][cc], a01, w2);
                    fma2(acc[2][cc], a10, w2);
                    fma2(acc[3][cc], a11, w2);
                }
            }
        }
    }

    // ---- horizontal add + relu(max2x2 + bias) ----
    const int p = tY * 8 + py, q = tX * 8 + px;
    const bool valid = (p < outDim) && (q < outDim);
    float res[NC];
    #pragma unroll
    for (int cc = 0; cc < NC; cc++) {
        float2 v0 = asF2(acc[0][cc]);
        float2 v1 = asF2(acc[1][cc]);
        float2 v2 = asF2(acc[2][cc]);
        float2 v3 = asF2(acc[3][cc]);
        float s0 = v0.x + v0.y, s1 = v1.x + v1.y;
        float s2 = v2.x + v2.y, s3 = v3.x + v3.y;
        res[cc] = fmaxf(fmaxf(fmaxf(s0, s1), fmaxf(s2, s3)) + bias[g + 4 * cc], 0.f);
    }

    if (out && valid) {
        float* o = out + ((size_t)((b * outDim + p) * outDim + q)) * COUT;
        #pragma unroll
        for (int cc = 0; cc < NC; cc++) o[g + 4 * cc] = res[cc];
    }

    if (meanAcc) {
        if (tid < COUT) sMean[tid] = 0.f;
        __syncthreads();
        if (valid) {
            #pragma unroll
            for (int cc = 0; cc < NC; cc++)
                atomicAdd(&sMean[g + 4 * cc], res[cc]);
        }
        __syncthreads();
        if (tid < COUT) atomicAdd(&meanAcc[b * COUT + tid], sMean[tid]);
    }
}

// ---------------------------------------------------------------------------
__global__ void zero_mean_kernel() { g_mean[threadIdx.x] = 0.f; }

// mean -> dense(32->64 relu) -> dense(64->32 relu) -> dense(32->6) + db3
__global__ void head_kernel(const float* __restrict__ D1, const float* __restrict__ db1,
                            const float* __restrict__ D2, const float* __restrict__ db2,
                            const float* __restrict__ D3, const float* __restrict__ db3)
{
    __shared__ float h0[16 * 32], h1[16 * 64], h2[16 * 32];
    int tid = threadIdx.x; // 256

    for (int i = tid; i < 512; i += 256) h0[i] = g_mean[i] * (1.0f / 900.0f);
    __syncthreads();

    for (int i = tid; i < 16 * 64; i += 256) {
        int bb = i >> 6, j = i & 63;
        float s = db1[j];
        #pragma unroll 8
        for (int c = 0; c < 32; c++) s += h0[bb * 32 + c] * D1[c * 64 + j];
        h1[i] = fmaxf(s, 0.f);
    }
    __syncthreads();

    for (int i = tid; i < 512; i += 256) {
        int bb = i >> 5, j = i & 31;
        float s = db2[j];
        #pragma unroll 8
        for (int c = 0; c < 64; c++) s += h1[bb * 64 + c] * D2[c * 32 + j];
        h2[i] = fmaxf(s, 0.f);
    }
    __syncthreads();

    if (tid < 96) {
        int bb = tid / 6, j = tid % 6;
        float s = db3[j];
        #pragma unroll 8
        for (int c = 0; c < 32; c++) s += h2[bb * 32 + c] * D3[c * 6 + j];
        g_theta[tid] = s;
    }
}

// ---------------------------------------------------------------------------
// Bilinear sampler: 8 threads per output pixel (4 channels each, float4).
// ---------------------------------------------------------------------------
__global__ __launch_bounds__(256)
void sampler_kernel(const float* __restrict__ x, float* __restrict__ out)
{
    int t = blockIdx.x * 256 + threadIdx.x;
    int lane = t & 7;
    int pix  = t >> 3;
    int c = pix & 255;
    int r = (pix >> 8) & 255;
    int b = pix >> 16;

    const float* th = g_theta + b * 6;
    float xs = -1.f + (float)c * (2.f / 255.f);
    float ys = -1.f + (float)r * (2.f / 255.f);
    float xS = th[0] * xs + th[1] * ys + th[2];
    float yS = th[3] * xs + th[4] * ys + th[5];
    float xf = 0.5f * ((xS + 1.f) * 254.f);
    float yf = 0.5f * ((yS + 1.f) * 254.f);

    int ix0 = (int)floorf(xf), iy0 = (int)floorf(yf);
    int ix1 = ix0 + 1, iy1 = iy0 + 1;
    ix0 = min(max(ix0, 0), 255); ix1 = min(max(ix1, 0), 255);
    iy0 = min(max(iy0, 0), 255); iy1 = min(max(iy1, 0), 255);

    float X0 = (float)ix0, X1 = (float)ix1, Y0 = (float)iy0, Y1 = (float)iy1;
    float wa = (X1 - xf) * (Y1 - yf);   // fm[y0, x0]
    float wb = (X1 - xf) * (yf - Y0);   // fm[y1, x0]
    float wc = (xf - X0) * (Y1 - yf);   // fm[y0, x1]
    float wd = (xf - X0) * (yf - Y0);   // fm[y1, x1]

    const float4* pa = (const float4*)(x + ((size_t)((b * 256 + iy0) * 256 + ix0)) * 32) + lane;
    const float4* pb = (const float4*)(x + ((size_t)((b * 256 + iy1) * 256 + ix0)) * 32) + lane;
    const float4* pc = (const float4*)(x + ((size_t)((b * 256 + iy0) * 256 + ix1)) * 32) + lane;
    const float4* pd = (const float4*)(x + ((size_t)((b * 256 + iy1) * 256 + ix1)) * 32) + lane;
    float4 Ia = *pa, Ib = *pb, Ic = *pc, Id = *pd;

    float4 o;
    o.x = wa * Ia.x + wb * Ib.x + wc * Ic.x + wd * Id.x;
    o.y = wa * Ia.y + wb * Ib.y + wc * Ic.y + wd * Id.y;
    o.z = wa * Ia.z + wb * Ib.z + wc * Ic.z + wd * Id.z;
    o.w = wa * Ia.w + wb * Ib.w + wc * Ic.w + wd * Id.w;
    ((float4*)out)[t] = o;
}

// ---------------------------------------------------------------------------
extern "C" void kernel_launch(void* const* d_in, const int* in_sizes, int n_in,
                              void* d_out, int out_size)
{
    const float* x   = (const float*)d_in[0];
    const float* W1  = (const float*)d_in[1];
    const float* b1  = (const float*)d_in[2];
    const float* W2  = (const float*)d_in[3];
    const float* b2  = (const float*)d_in[4];
    const float* W3  = (const float*)d_in[5];
    const float* b3  = (const float*)d_in[6];
    const float* D1  = (const float*)d_in[7];
    const float* db1 = (const float*)d_in[8];
    const float* D2  = (const float*)d_in[9];
    const float* db2 = (const float*)d_in[10];
    const float* D3  = (const float*)d_in[11];
    const float* db3 = (const float*)d_in[12];
    float* out = (float*)d_out;

    float *p1, *p2, *mean_;
    cudaGetSymbolAddress((void**)&p1, g_pool1);
    cudaGetSymbolAddress((void**)&p2, g_pool2);
    cudaGetSymbolAddress((void**)&mean_, g_mean);

    // smem sizes (floats): input 324*(CIN+4), weights 9*COUT*(CIN+2)
    const int SMEM1 = (324 * 36 + 9 * 16 * 34) * 4;   // 66240  -> 3 blocks/SM
    const int SMEM2 = (324 * 20 + 9 * 32 * 18) * 4;   // 46656  -> 4 blocks/SM
    const int SMEM3 = (324 * 36 + 9 * 32 * 34) * 4;   // 85824  -> 2 blocks/SM
    cudaFuncSetAttribute((const void*)conv_pool_kernel<32, 16>,
                         cudaFuncAttributeMaxDynamicSharedMemorySize, SMEM1);
    cudaFuncSetAttribute((const void*)conv_pool_kernel<16, 32>,
                         cudaFuncAttributeMaxDynamicSharedMemorySize, SMEM2);
    cudaFuncSetAttribute((const void*)conv_pool_kernel<32, 32>,
                         cudaFuncAttributeMaxDynamicSharedMemorySize, SMEM3);

    zero_mean_kernel<<<1, 512>>>();

    // stage 1: (16,256,256,32) -> (16,127,127,16) ; tiles 16x16
    conv_pool_kernel<32, 16><<<dim3(16 * 16, 16), 256, SMEM1>>>(
        x, 256, W1, b1, p1, 127, 16, nullptr);

    // stage 2: (16,127,127,16) -> (16,62,62,32) ; tiles 8x8
    conv_pool_kernel<16, 32><<<dim3(8 * 8, 16), 256, SMEM2>>>(
        p1, 127, W2, b2, p2, 62, 8, nullptr);

    // stage 3: (16,62,62,32) -> global-mean sums (pooled3 never stored)
    conv_pool_kernel<32, 32><<<dim3(4 * 4, 16), 256, SMEM3>>>(
        p2, 62, W3, b3, nullptr, 30, 4, mean_);

    head_kernel<<<1, 256>>>(D1, db1, D2, db2, D3, db3);

    // sampler: 16*256*256 pixels * 8 threads = 8.39M threads
    sampler_kernel<<<32768, 256>>>(x, out);
}

// round 3
// speedup vs baseline: 1.5744x; 1.2060x over previous
#include <cuda_runtime.h>
#include <cstdint>

// ---------------------------------------------------------------------------
// STN: conv(3x3)+relu+pool x3 -> mean -> dense x3 -> theta -> bilinear sample
// ---------------------------------------------------------------------------

typedef unsigned long long ull;

__device__ float g_pool1[16 * 127 * 127 * 16];
__device__ float g_pool2[16 * 62 * 62 * 32];
__device__ float g_mean[16 * 32];
__device__ float g_theta[16 * 6];

__device__ __forceinline__ void fma2(ull& d, ull a, ull b) {
    asm("fma.rn.f32x2 %0, %1, %2, %0;" : "+l"(d) : "l"(a), "l"(b));
}
__device__ __forceinline__ float2 asF2(ull v) {
    float2 r;
    r.x = __uint_as_float((unsigned)(v & 0xffffffffULL));
    r.y = __uint_as_float((unsigned)(v >> 32));
    return r;
}

// ---------------------------------------------------------------------------
// Fused conv3x3(VALID)+bias+relu+maxpool2 (+optional mean accumulation)
// fp32x2 packed over input-channel pairs; horizontal add at the end.
// Each thread: 2x4 conv positions (= 1x2 pooled pixels) x 4 output channels.
// Per c2: 4x6 input window (24 LDS.64, reused across all 9 taps) +
//         9*4 weight LDS.64 -> 288 FFMA2 (83% FMA issue share).
// Block: 128 thr = 4 x-slots * TILE_PY y-slots * GROUPS channel groups.
// Pooled tile: 8 wide x TILE_PY tall.
// ---------------------------------------------------------------------------
template<int CIN, int COUT, int GROUPS, int TILE_PY>
__global__ __launch_bounds__(128, 3)
void conv_pool_kernel(const float* __restrict__ in, int inDim,
                      const float* __restrict__ w, const float* __restrict__ bias,
                      float* __restrict__ out, int outDim, int tilesX,
                      float* __restrict__ meanAcc)
{
    constexpr int NC   = COUT / GROUPS;     // = 4 channels per thread
    constexpr int ISTR = CIN + 2;           // even, ISTR/2 odd -> bank spread
    constexpr int WSTR = CIN + 2;
    constexpr int TW   = 18;                // input tile width (16 conv cols + 2)
    constexpr int TH   = 2 * TILE_PY + 2;   // input tile height
    extern __shared__ float smem[];
    float* sIn = smem;                      // TH*TW*ISTR
    float* sW  = smem + TH * TW * ISTR;     // 9*COUT*WSTR
    __shared__ float sMean[COUT];

    const int tid = threadIdx.x;
    const int b  = blockIdx.y;
    const int tX = blockIdx.x % tilesX;
    const int tY = blockIdx.x / tilesX;
    const int y0 = tY * TILE_PY * 2, x0 = tX * 16;

    // ---- weights: w[k][ci][co] -> sW[k][co][ci] ----
    constexpr int WTOT = 9 * CIN * COUT;
    for (int i = tid; i < WTOT; i += 128) {
        int co = i % COUT;
        int rest = i / COUT;
        int ci = rest % CIN;
        int k  = rest / CIN;
        sW[(k * COUT + co) * WSTR + ci] = w[i];
    }

    // ---- input window THxTWxCIN (channel-contiguous) ----
    constexpr int NCI4 = CIN / 4;
    for (int i = tid; i < TH * TW * NCI4; i += 128) {
        int ci4 = i % NCI4;
        int p   = i / NCI4;
        int ly = p / TW, lx = p - ly * TW;
        int gy = y0 + ly, gx = x0 + lx;
        float4 v = make_float4(0.f, 0.f, 0.f, 0.f);
        if (gy < inDim && gx < inDim)
            v = *(const float4*)(in + ((size_t)((b * inDim + gy) * inDim + gx)) * CIN + ci4 * 4);
        float* d = sIn + p * ISTR + ci4 * 4;        // 8B-aligned (ISTR even)
        *(ull*)(d)     = *(const ull*)&v.x;
        *(ull*)(d + 2) = *(const ull*)&v.z;
    }
    __syncthreads();

    const int g    = tid % GROUPS;
    const int slot = tid / GROUPS;
    const int sx   = slot % 4;              // covers conv cols 4sx..4sx+3
    const int py   = slot / 4;              // pooled row within tile

    ull acc[2][4][NC];
    #pragma unroll
    for (int i = 0; i < 2; i++)
        #pragma unroll
        for (int j = 0; j < 4; j++)
            #pragma unroll
            for (int k = 0; k < NC; k++) acc[i][j][k] = 0ULL;

    const float* ibase = sIn + ((2 * py) * TW + 4 * sx) * ISTR;
    const float* wbase = sW + g * WSTR;

    #pragma unroll 1
    for (int c2 = 0; c2 < CIN / 2; ++c2) {
        ull win[4][6];
        #pragma unroll
        for (int r = 0; r < 4; ++r)
            #pragma unroll
            for (int c = 0; c < 6; ++c)
                win[r][c] = *(const ull*)(ibase + (r * TW + c) * ISTR + 2 * c2);
        #pragma unroll
        for (int t = 0; t < 9; ++t) {
            const int ky = t / 3, kx = t % 3;
            #pragma unroll
            for (int cc = 0; cc < NC; ++cc) {
                ull w2 = *(const ull*)(wbase + (t * COUT + GROUPS * cc) * WSTR + 2 * c2);
                #pragma unroll
                for (int pr = 0; pr < 2; ++pr)
                    #pragma unroll
                    for (int pc = 0; pc < 4; ++pc)
                        fma2(acc[pr][pc][cc], win[pr + ky][pc + kx], w2);
            }
        }
    }

    // ---- horizontal add + relu(max2x2 + bias), two pooled pixels ----
    const int p = tY * TILE_PY + py;
    if (meanAcc) {
        if (tid < COUT) sMean[tid] = 0.f;
        __syncthreads();
    }
    #pragma unroll
    for (int j = 0; j < 2; ++j) {
        const int q = tX * 8 + 2 * sx + j;
        const bool valid = (p < outDim) && (q < outDim);
        float res[NC];
        #pragma unroll
        for (int cc = 0; cc < NC; ++cc) {
            float2 v00 = asF2(acc[0][2 * j][cc]);
            float2 v01 = asF2(acc[0][2 * j + 1][cc]);
            float2 v10 = asF2(acc[1][2 * j][cc]);
            float2 v11 = asF2(acc[1][2 * j + 1][cc]);
            float s0 = v00.x + v00.y, s1 = v01.x + v01.y;
            float s2 = v10.x + v10.y, s3 = v11.x + v11.y;
            res[cc] = fmaxf(fmaxf(fmaxf(s0, s1), fmaxf(s2, s3)) + bias[g + GROUPS * cc], 0.f);
        }
        if (out && valid) {
            float* o = out + ((size_t)((b * outDim + p) * outDim + q)) * COUT;
            #pragma unroll
            for (int cc = 0; cc < NC; ++cc) o[g + GROUPS * cc] = res[cc];
        }
        if (meanAcc && valid) {
            #pragma unroll
            for (int cc = 0; cc < NC; ++cc)
                atomicAdd(&sMean[g + GROUPS * cc], res[cc]);
        }
    }
    if (meanAcc) {
        __syncthreads();
        if (tid < COUT) atomicAdd(&meanAcc[b * COUT + tid], sMean[tid]);
    }
}

// ---------------------------------------------------------------------------
__global__ void zero_mean_kernel() { g_mean[threadIdx.x] = 0.f; }

__global__ void head_kernel(const float* __restrict__ D1, const float* __restrict__ db1,
                            const float* __restrict__ D2, const float* __restrict__ db2,
                            const float* __restrict__ D3, const float* __restrict__ db3)
{
    __shared__ float h0[16 * 32], h1[16 * 64], h2[16 * 32];
    int tid = threadIdx.x; // 256

    for (int i = tid; i < 512; i += 256) h0[i] = g_mean[i] * (1.0f / 900.0f);
    __syncthreads();

    for (int i = tid; i < 16 * 64; i += 256) {
        int bb = i >> 6, j = i & 63;
        float s = db1[j];
        #pragma unroll 8
        for (int c = 0; c < 32; c++) s += h0[bb * 32 + c] * D1[c * 64 + j];
        h1[i] = fmaxf(s, 0.f);
    }
    __syncthreads();

    for (int i = tid; i < 512; i += 256) {
        int bb = i >> 5, j = i & 31;
        float s = db2[j];
        #pragma unroll 8
        for (int c = 0; c < 64; c++) s += h1[bb * 64 + c] * D2[c * 32 + j];
        h2[i] = fmaxf(s, 0.f);
    }
    __syncthreads();

    if (tid < 96) {
        int bb = tid / 6, j = tid % 6;
        float s = db3[j];
        #pragma unroll 8
        for (int c = 0; c < 32; c++) s += h2[bb * 32 + c] * D3[c * 6 + j];
        g_theta[tid] = s;
    }
}

// ---------------------------------------------------------------------------
__global__ __launch_bounds__(256)
void sampler_kernel(const float* __restrict__ x, float* __restrict__ out)
{
    int t = blockIdx.x * 256 + threadIdx.x;
    int lane = t & 7;
    int pix  = t >> 3;
    int c = pix & 255;
    int r = (pix >> 8) & 255;
    int b = pix >> 16;

    const float* th = g_theta + b * 6;
    float xs = -1.f + (float)c * (2.f / 255.f);
    float ys = -1.f + (float)r * (2.f / 255.f);
    float xS = th[0] * xs + th[1] * ys + th[2];
    float yS = th[3] * xs + th[4] * ys + th[5];
    float xf = 0.5f * ((xS + 1.f) * 254.f);
    float yf = 0.5f * ((yS + 1.f) * 254.f);

    int ix0 = (int)floorf(xf), iy0 = (int)floorf(yf);
    int ix1 = ix0 + 1, iy1 = iy0 + 1;
    ix0 = min(max(ix0, 0), 255); ix1 = min(max(ix1, 0), 255);
    iy0 = min(max(iy0, 0), 255); iy1 = min(max(iy1, 0), 255);

    float X0 = (float)ix0, X1 = (float)ix1, Y0 = (float)iy0, Y1 = (float)iy1;
    float wa = (X1 - xf) * (Y1 - yf);
    float wb = (X1 - xf) * (yf - Y0);
    float wc = (xf - X0) * (Y1 - yf);
    float wd = (xf - X0) * (yf - Y0);

    const float4* pa = (const float4*)(x + ((size_t)((b * 256 + iy0) * 256 + ix0)) * 32) + lane;
    const float4* pb = (const float4*)(x + ((size_t)((b * 256 + iy1) * 256 + ix0)) * 32) + lane;
    const float4* pc = (const float4*)(x + ((size_t)((b * 256 + iy0) * 256 + ix1)) * 32) + lane;
    const float4* pd = (const float4*)(x + ((size_t)((b * 256 + iy1) * 256 + ix1)) * 32) + lane;
    float4 Ia = *pa, Ib = *pb, Ic = *pc, Id = *pd;

    float4 o;
    o.x = wa * Ia.x + wb * Ib.x + wc * Ic.x + wd * Id.x;
    o.y = wa * Ia.y + wb * Ib.y + wc * Ic.y + wd * Id.y;
    o.z = wa * Ia.z + wb * Ib.z + wc * Ic.z + wd * Id.z;
    o.w = wa * Ia.w + wb * Ib.w + wc * Ic.w + wd * Id.w;
    ((float4*)out)[t] = o;
}

// ---------------------------------------------------------------------------
extern "C" void kernel_launch(void* const* d_in, const int* in_sizes, int n_in,
                              void* d_out, int out_size)
{
    const float* x   = (const float*)d_in[0];
    const float* W1  = (const float*)d_in[1];
    const float* b1  = (const float*)d_in[2];
    const float* W2  = (const float*)d_in[3];
    const float* b2  = (const float*)d_in[4];
    const float* W3  = (const float*)d_in[5];
    const float* b3  = (const float*)d_in[6];
    const float* D1  = (const float*)d_in[7];
    const float* db1 = (const float*)d_in[8];
    const float* D2  = (const float*)d_in[9];
    const float* db2 = (const float*)d_in[10];
    const float* D3  = (const float*)d_in[11];
    const float* db3 = (const float*)d_in[12];
    float* out = (float*)d_out;

    float *p1, *p2, *mean_;
    cudaGetSymbolAddress((void**)&p1, g_pool1);
    cudaGetSymbolAddress((void**)&p2, g_pool2);
    cudaGetSymbolAddress((void**)&mean_, g_mean);

    // smem: input TH*TW*(CIN+2) + weights 9*COUT*(CIN+2), floats
    const int SMEM1 = (18 * 18 * 34 + 9 * 16 * 34) * 4;   // 63648
    const int SMEM2 = (10 * 18 * 18 + 9 * 32 * 18) * 4;   // 33696
    const int SMEM3 = (10 * 18 * 34 + 9 * 32 * 34) * 4;   // 63648
    cudaFuncSetAttribute((const void*)conv_pool_kernel<32, 16, 4, 8>,
                         cudaFuncAttributeMaxDynamicSharedMemorySize, SMEM1);
    cudaFuncSetAttribute((const void*)conv_pool_kernel<16, 32, 8, 4>,
                         cudaFuncAttributeMaxDynamicSharedMemorySize, SMEM2);
    cudaFuncSetAttribute((const void*)conv_pool_kernel<32, 32, 8, 4>,
                         cudaFuncAttributeMaxDynamicSharedMemorySize, SMEM3);

    zero_mean_kernel<<<1, 512>>>();

    // stage 1: (16,256,256,32) -> (16,127,127,16); tiles 8x8 pooled
    conv_pool_kernel<32, 16, 4, 8><<<dim3(16 * 16, 16), 128, SMEM1>>>(
        x, 256, W1, b1, p1, 127, 16, nullptr);

    // stage 2: (16,127,127,16) -> (16,62,62,32); tiles 8x4 pooled
    conv_pool_kernel<16, 32, 8, 4><<<dim3(8 * 16, 16), 128, SMEM2>>>(
        p1, 127, W2, b2, p2, 62, 8, nullptr);

    // stage 3: (16,62,62,32) -> mean sums; tiles 8x4 pooled
    conv_pool_kernel<32, 32, 8, 4><<<dim3(4 * 8, 16), 128, SMEM3>>>(
        p2, 62, W3, b3, nullptr, 30, 4, mean_);

    head_kernel<<<1, 256>>>(D1, db1, D2, db2, D3, db3);

    sampler_kernel<<<32768, 256>>>(x, out);
}